// round 11
// baseline (speedup 1.0000x reference)
#include <cuda_runtime.h>
#include <cuda_bf16.h>
#include <cuda_fp16.h>
#include <cstdint>

#define Bn 8
#define Cn 256
#define Ln 2048
#define Dn 32

// scratch (device globals; no cudaMalloc allowed)
__device__ __nv_bfloat16 g_Qb[Bn * Ln * Dn];   // [b][l][d]  pre-scaled by scale*log2e
__device__ __nv_bfloat16 g_Kb[Bn * Ln * Dn];   // [b][l][d]
__device__ uint8_t       g_V8[Bn * Cn * Ln];   // [b][c][l]  e4m3

// ============================ helpers ======================================
__device__ __forceinline__ uint32_t smem_to_u32(const void* p) {
    uint32_t a;
    asm("{ .reg .u64 t; cvta.to.shared.u64 t, %1; cvt.u32.u64 %0, t; }" : "=r"(a) : "l"(p));
    return a;
}
__device__ __forceinline__ float ex2f(float x) {
    float r; asm("ex2.approx.ftz.f32 %0, %1;" : "=f"(r) : "f"(x)); return r;
}
#define CVT_BF16X2(res, a, b) \
    asm("cvt.rn.bf16x2.f32 %0, %1, %2;" : "=r"(res) : "f"(b), "f"(a))
#define CVT_F16X2(res, a, b) \
    asm("cvt.rn.f16x2.f32 %0, %1, %2;" : "=r"(res) : "f"(b), "f"(a))
// res(u16) = {lo: a, hi: b} packed e4m3
#define CVT_E4M3X2(res, a, b) \
    asm("cvt.rn.satfinite.e4m3x2.f32 %0, %1, %2;" : "=h"(res) : "f"(b), "f"(a))

__device__ __forceinline__ void ldmatrix_x4(uint32_t& r0, uint32_t& r1, uint32_t& r2, uint32_t& r3, uint32_t addr) {
    asm volatile("ldmatrix.sync.aligned.m8n8.x4.shared.b16 {%0,%1,%2,%3}, [%4];"
                 : "=r"(r0), "=r"(r1), "=r"(r2), "=r"(r3) : "r"(addr));
}
__device__ __forceinline__ void ldmatrix_x2(uint32_t& r0, uint32_t& r1, uint32_t addr) {
    asm volatile("ldmatrix.sync.aligned.m8n8.x2.shared.b16 {%0,%1}, [%2];"
                 : "=r"(r0), "=r"(r1) : "r"(addr));
}
__device__ __forceinline__ void mma_bf16(float& c0, float& c1, float& c2, float& c3,
                                         uint32_t a0, uint32_t a1, uint32_t a2, uint32_t a3,
                                         uint32_t b0, uint32_t b1) {
    asm volatile("mma.sync.aligned.m16n8k16.row.col.f32.bf16.bf16.f32 "
                 "{%0,%1,%2,%3}, {%4,%5,%6,%7}, {%8,%9}, {%0,%1,%2,%3};"
                 : "+f"(c0), "+f"(c1), "+f"(c2), "+f"(c3)
                 : "r"(a0), "r"(a1), "r"(a2), "r"(a3), "r"(b0), "r"(b1));
}
__device__ __forceinline__ void mma_fp16(float& c0, float& c1, float& c2, float& c3,
                                         uint32_t a0, uint32_t a1, uint32_t a2, uint32_t a3,
                                         uint32_t b0, uint32_t b1) {
    asm volatile("mma.sync.aligned.m16n8k16.row.col.f32.f16.f16.f32 "
                 "{%0,%1,%2,%3}, {%4,%5,%6,%7}, {%8,%9}, {%0,%1,%2,%3};"
                 : "+f"(c0), "+f"(c1), "+f"(c2), "+f"(c3)
                 : "r"(a0), "r"(a1), "r"(a2), "r"(a3), "r"(b0), "r"(b1));
}
__device__ __forceinline__ void mma_fp8(float& c0, float& c1, float& c2, float& c3,
                                        uint32_t a0, uint32_t a1, uint32_t a2, uint32_t a3,
                                        uint32_t b0, uint32_t b1) {
    asm volatile("mma.sync.aligned.m16n8k32.row.col.f32.e4m3.e4m3.f32 "
                 "{%0,%1,%2,%3}, {%4,%5,%6,%7}, {%8,%9}, {%0,%1,%2,%3};"
                 : "+f"(c0), "+f"(c1), "+f"(c2), "+f"(c3)
                 : "r"(a0), "r"(a1), "r"(a2), "r"(a3), "r"(b0), "r"(b1));
}
__device__ __forceinline__ uint32_t lds32(uint32_t addr) {
    uint32_t v; asm volatile("ld.shared.b32 %0, [%1];" : "=r"(v) : "r"(addr)); return v;
}
__device__ __forceinline__ void sts16(uint32_t addr, uint16_t v) {
    asm volatile("st.shared.u16 [%0], %1;" :: "r"(addr), "h"(v));
}
__device__ __forceinline__ void cp_async16(uint32_t saddr, const void* gptr) {
    asm volatile("cp.async.cg.shared.global [%0], [%1], 16;" :: "r"(saddr), "l"(gptr));
}
#define CP_COMMIT() asm volatile("cp.async.commit_group;" ::: "memory")
#define CP_WAIT0()  asm volatile("cp.async.wait_group 0;" ::: "memory")
#define BAR_SYNC(id, n) asm volatile("bar.sync %0, %1;" :: "r"(id), "r"(n) : "memory")

// ===========================================================================
// Kernel 1: QKV projection as HMMA GEMM (W loaded fp32, cvt in-register).
// grid (L/128, B), 512 threads. Warp w: mg = w&1 (64 l), nh = w>>1 (40 rows).
// V output now e4m3 bytes [b][c][l].
// ===========================================================================
#define QKV_SMEM 69632

__global__ __launch_bounds__(512) void qkv_gemm(
    const float* __restrict__ x,
    const float* __restrict__ Wq, const float* __restrict__ bq,
    const float* __restrict__ Wk, const float* __restrict__ bk,
    const float* __restrict__ Wv, const float* __restrict__ bv)
{
    extern __shared__ __align__(16) char qsmraw[];
    uint32_t* xs = reinterpret_cast<uint32_t*>(qsmraw);

    const int b = blockIdx.y, l0 = blockIdx.x * 128, t = threadIdx.x;
    const float* xb = x + (size_t)b * Cn * Ln;

    for (int idx = t; idx < 128 * 128; idx += 512) {
        int cp = idx >> 7, l = idx & 127;
        float f0 = xb[(size_t)(2 * cp) * Ln + l0 + l];
        float f1 = xb[(size_t)(2 * cp + 1) * Ln + l0 + l];
        uint32_t p; CVT_F16X2(p, f0, f1);
        xs[l * 132 + cp] = p;
    }
    __syncthreads();

    const int w = t >> 5, lane = t & 31;
    const int mg = w & 1, nh = w >> 1;
    const int nbase = nh * 40;

    const float* wp[5];
    #pragma unroll
    for (int nt = 0; nt < 5; ++nt) {
        int n0 = nbase + nt * 8;
        const float* src;
        if (n0 < 32)      src = Wq + n0 * Cn;
        else if (n0 < 64) src = Wk + (n0 - 32) * Cn;
        else              src = Wv + (n0 - 64) * Cn;
        wp[nt] = src + (lane >> 2) * Cn + (lane & 3) * 2;
    }

    float of[4][5][4];
    #pragma unroll
    for (int m = 0; m < 4; ++m)
        #pragma unroll
        for (int n = 0; n < 5; ++n)
            #pragma unroll
            for (int k = 0; k < 4; ++k) of[m][n][k] = 0.f;

    const uint32_t abase = smem_to_u32(xs)
        + (uint32_t)((mg * 64 + (lane & 15)) * 132) * 4 + ((lane >> 4) & 1) * 16;

    for (int ks = 0; ks < 16; ++ks) {
        uint32_t aq[4][4];
        #pragma unroll
        for (int mt = 0; mt < 4; ++mt)
            ldmatrix_x4(aq[mt][0], aq[mt][1], aq[mt][2], aq[mt][3],
                        abase + (uint32_t)(mt * 16 * 132) * 4 + ks * 32);
        #pragma unroll
        for (int nt = 0; nt < 5; ++nt) {
            float2 wa = __ldg(reinterpret_cast<const float2*>(wp[nt] + ks * 16));
            float2 wb = __ldg(reinterpret_cast<const float2*>(wp[nt] + ks * 16 + 8));
            uint32_t b0, b1;
            CVT_F16X2(b0, wa.x, wa.y);
            CVT_F16X2(b1, wb.x, wb.y);
            #pragma unroll
            for (int mt = 0; mt < 4; ++mt)
                mma_fp16(of[mt][nt][0], of[mt][nt][1], of[mt][nt][2], of[mt][nt][3],
                         aq[mt][0], aq[mt][1], aq[mt][2], aq[mt][3], b0, b1);
        }
    }
    __syncthreads();

    uint8_t* vt = reinterpret_cast<uint8_t*>(qsmraw);   // [256][144] e4m3
    const float qs = 1.4426950408889634f * 0.17677669529663687f;    // log2e / sqrt(D)

    #pragma unroll
    for (int nt = 0; nt < 5; ++nt) {
        int n0 = nbase + nt * 8;
        int d = n0 + (lane & 3) * 2;
        float2 bs;
        if (n0 < 32)      bs = __ldg(reinterpret_cast<const float2*>(bq + d));
        else if (n0 < 64) bs = __ldg(reinterpret_cast<const float2*>(bk + d - 32));
        else              bs = __ldg(reinterpret_cast<const float2*>(bv + d - 64));
        #pragma unroll
        for (int mt = 0; mt < 4; ++mt) {
            const int ll = mg * 64 + mt * 16 + (lane >> 2);
            const int lq = l0 + ll;
            float v0 = of[mt][nt][0] + bs.x, v1 = of[mt][nt][1] + bs.y;
            float v2 = of[mt][nt][2] + bs.x, v3 = of[mt][nt][3] + bs.y;
            if (n0 < 32) {
                uint32_t p0, p1;
                CVT_BF16X2(p0, v0 * qs, v1 * qs);
                CVT_BF16X2(p1, v2 * qs, v3 * qs);
                *reinterpret_cast<uint32_t*>(&g_Qb[((size_t)b * Ln + lq) * Dn + d])     = p0;
                *reinterpret_cast<uint32_t*>(&g_Qb[((size_t)b * Ln + lq + 8) * Dn + d]) = p1;
            } else if (n0 < 64) {
                int dk = d - 32;
                uint32_t p0, p1;
                CVT_BF16X2(p0, v0, v1);
                CVT_BF16X2(p1, v2, v3);
                *reinterpret_cast<uint32_t*>(&g_Kb[((size_t)b * Ln + lq) * Dn + dk])     = p0;
                *reinterpret_cast<uint32_t*>(&g_Kb[((size_t)b * Ln + lq + 8) * Dn + dk]) = p1;
            } else {
                int c = d - 64;
                uint16_t pA, pB;
                CVT_E4M3X2(pA, v0, v1);   // lo=v0 (row c), hi=v1 (row c+1)
                CVT_E4M3X2(pB, v2, v3);
                vt[c * 144 + ll]           = (uint8_t)(pA & 0xFF);
                vt[(c + 1) * 144 + ll]     = (uint8_t)(pA >> 8);
                vt[c * 144 + ll + 8]       = (uint8_t)(pB & 0xFF);
                vt[(c + 1) * 144 + ll + 8] = (uint8_t)(pB >> 8);
            }
        }
    }
    __syncthreads();

    // coalesced V store: [c][l] bytes, uint4 along l
    uint8_t* Vg = g_V8 + (size_t)b * Cn * Ln;
    for (int idx = t; idx < 256 * 8; idx += 512) {
        int c = idx >> 3, k16 = idx & 7;
        *reinterpret_cast<uint4*>(Vg + (size_t)c * Ln + l0 + k16 * 16) =
            *reinterpret_cast<const uint4*>(&vt[c * 144 + k16 * 16]);
    }
}

// ===========================================================================
// Kernel 2: flash attention, QK bf16 HMMA + PV fp8 (e4m3) HMMA.
// grid (L/128, 2, B) = 256 CTAs (one wave), 256 threads, 2 CTAs/SM.
// Warp w: qg = w>>1 (16 q rows), ch = w&1 (64 ch; own 64-j half of S).
// Smem (bytes):
//   [0, 18432)   prologue Q [128][40] bf16 (10240) / P tiles [qt][qg][16][144] e4m3
//   SM_K(bi)     K [2][128][40] bf16   (10240 each)
//   SM_V(bi)     V [2][128c][144] e4m3 (18432 each; buf0 reused f32 [64][68] epilogue)
//   SM_LS        row-sum exchange (4096)
// ===========================================================================
#define SM_P(qt, qg) ((qt) * 9216 + (qg) * 2304)
#define SM_K(bi) (18432 + (bi) * 10240)
#define SM_V(bi) (38912 + (bi) * 18432)
#define SM_LS    75776
#define SM_TOTAL 79872

__global__ __launch_bounds__(256, 2) void attn_kernel(
    const float* __restrict__ x,
    const float* __restrict__ gamma,
    float* __restrict__ out)
{
    extern __shared__ __align__(16) char dsm[];
    const int b = blockIdx.z, ch_half = blockIdx.y, i0 = blockIdx.x * 128;
    const int t = threadIdx.x;
    const int w = t >> 5, lane = t & 31;
    const int qg = w >> 1, ch = w & 1;

    const uint32_t sbase = smem_to_u32(dsm);
    __nv_bfloat16* Qsm = reinterpret_cast<__nv_bfloat16*>(dsm);

    const __nv_bfloat16* Qg = &g_Qb[((size_t)b * Ln + i0) * Dn];
    const __nv_bfloat16* Kg = &g_Kb[(size_t)b * Ln * Dn];
    const uint8_t* Vg = &g_V8[((size_t)b * Cn + ch_half * 128) * Ln];

    // stage Q tile: 128 q x 32 d (512 uint4, 2/thread)
    #pragma unroll
    for (int i = 0; i < 2; ++i) {
        int idx = t + i * 256;
        int q = idx >> 2, dc = idx & 3;
        uint4 v = *reinterpret_cast<const uint4*>(Qg + (size_t)q * Dn + dc * 8);
        *reinterpret_cast<uint4*>(&Qsm[q * 40 + dc * 8]) = v;
    }

    // prologue: chunk 0. K: 512 cp (2/thread); V: 1024 cp (4/thread)
    {
        #pragma unroll
        for (int i = 0; i < 2; ++i) {
            int idx = t + i * 256;
            int j = idx >> 2, dc = idx & 3;
            cp_async16(sbase + SM_K(0) + j * 80 + dc * 16, Kg + (size_t)j * Dn + dc * 8);
        }
        #pragma unroll
        for (int i = 0; i < 4; ++i) {
            int idx = t + i * 256;
            int c = idx >> 3, jc = idx & 7;
            cp_async16(sbase + SM_V(0) + c * 144 + jc * 16, Vg + (size_t)c * Ln + jc * 16);
        }
    }
    CP_COMMIT();
    __syncthreads();

    // Q a-frags for both q-tiles (Q smem dead after -> region becomes P tiles)
    uint32_t aq[2][2][4];
    #pragma unroll
    for (int qt = 0; qt < 2; ++qt) {
        uint32_t base = sbase
            + ((qt * 64 + qg * 16 + (lane & 15)) * 40 + ((lane >> 4) & 1) * 8) * 2;
        ldmatrix_x4(aq[qt][0][0], aq[qt][0][1], aq[qt][0][2], aq[qt][0][3], base);
        ldmatrix_x4(aq[qt][1][0], aq[qt][1][1], aq[qt][1][2], aq[qt][1][3], base + 32);
    }

    const uint32_t kb_lane = (lane & 7) * 80 + ((lane >> 3) & 1) * 16;
    const int barid = 1 + qg;

    float of[2][8][4];
    #pragma unroll
    for (int qt = 0; qt < 2; ++qt)
        #pragma unroll
        for (int n = 0; n < 8; ++n)
            #pragma unroll
            for (int k = 0; k < 4; ++k) of[qt][n][k] = 0.f;
    float lsum[2][2] = {{0.f, 0.f}, {0.f, 0.f}};

// QK (bf16) for q-tile QT over own 64-j half -> exp -> e4m3 bytes into P tile
#define QK_PHASE(QT) do {                                                      \
    const uint32_t kh = ks_u + (uint32_t)(ch * 64) * 80 + kb_lane;             \
    const uint32_t pb = sbase + SM_P(QT, qg) + (lane >> 2) * 144               \
                      + ch * 64 + (lane & 3) * 2;                              \
    _Pragma("unroll")                                                          \
    for (int jt = 0; jt < 8; ++jt) {                                           \
        float s0 = 0.f, s1 = 0.f, s2 = 0.f, s3 = 0.f;                          \
        uint32_t b0, b1;                                                       \
        uint32_t kaddr = kh + jt * 640;                                        \
        ldmatrix_x2(b0, b1, kaddr);                                            \
        mma_bf16(s0, s1, s2, s3, aq[QT][0][0], aq[QT][0][1],                   \
                 aq[QT][0][2], aq[QT][0][3], b0, b1);                          \
        ldmatrix_x2(b0, b1, kaddr + 32);                                       \
        mma_bf16(s0, s1, s2, s3, aq[QT][1][0], aq[QT][1][1],                   \
                 aq[QT][1][2], aq[QT][1][3], b0, b1);                          \
        float e0 = ex2f(s0), e1 = ex2f(s1), e2 = ex2f(s2), e3 = ex2f(s3);      \
        lsum[QT][0] += e0 + e1;                                                \
        lsum[QT][1] += e2 + e3;                                                \
        uint16_t p01, p23;                                                     \
        CVT_E4M3X2(p01, e0, e1);                                               \
        CVT_E4M3X2(p23, e2, e3);                                               \
        sts16(pb + jt * 8, p01);                                               \
        sts16(pb + 8 * 144 + jt * 8, p23);                                     \
    }                                                                          \
} while (0)

// PV (fp8) for q-tile QT: full 128-j chunk, 8 n-tiles, 4 k32-MMAs each
#define PV_PHASE(QT) do {                                                      \
    uint32_t ap[4][4];                                                         \
    const uint32_t pbb = sbase + SM_P(QT, qg) + (lane >> 2) * 144              \
                       + (lane & 3) * 4;                                       \
    _Pragma("unroll")                                                          \
    for (int km = 0; km < 4; ++km) {                                           \
        uint32_t a = pbb + km * 32;                                            \
        ap[km][0] = lds32(a);                                                  \
        ap[km][1] = lds32(a + 1152);                                           \
        ap[km][2] = lds32(a + 16);                                             \
        ap[km][3] = lds32(a + 1168);                                           \
    }                                                                          \
    _Pragma("unroll")                                                          \
    for (int nt = 0; nt < 8; ++nt) {                                           \
        uint32_t vb = vs_u + (uint32_t)(ch * 64 + nt * 8 + (lane >> 2)) * 144  \
                    + (lane & 3) * 4;                                          \
        _Pragma("unroll")                                                      \
        for (int km = 0; km < 4; ++km) {                                       \
            uint32_t b0 = lds32(vb + km * 32);                                 \
            uint32_t b1 = lds32(vb + km * 32 + 16);                            \
            mma_fp8(of[QT][nt][0], of[QT][nt][1], of[QT][nt][2], of[QT][nt][3],\
                    ap[km][0], ap[km][1], ap[km][2], ap[km][3], b0, b1);       \
        }                                                                      \
    }                                                                          \
} while (0)

    for (int cidx = 0; cidx < Ln / 128; ++cidx) {
        CP_WAIT0();
        __syncthreads();   // buffers + P tiles free for this chunk

        // issue chunk cidx+1
        if (cidx + 1 < Ln / 128) {
            int j0n = (cidx + 1) * 128;
            int bi = (cidx + 1) & 1;
            #pragma unroll
            for (int i = 0; i < 2; ++i) {
                int idx = t + i * 256;
                int j = idx >> 2, dc = idx & 3;
                cp_async16(sbase + SM_K(bi) + j * 80 + dc * 16,
                           Kg + (size_t)(j0n + j) * Dn + dc * 8);
            }
            #pragma unroll
            for (int i = 0; i < 4; ++i) {
                int idx = t + i * 256;
                int c = idx >> 3, jc = idx & 7;
                cp_async16(sbase + SM_V(bi) + c * 144 + jc * 16,
                           Vg + (size_t)c * Ln + j0n + jc * 16);
            }
        }
        CP_COMMIT();

        const uint32_t ks_u = sbase + SM_K(cidx & 1);
        const uint32_t vs_u = sbase + SM_V(cidx & 1);

        QK_PHASE(0);
        QK_PHASE(1);
        BAR_SYNC(barid, 64);     // pair warp published its j-halves of P
        PV_PHASE(0);
        PV_PHASE(1);
    }

    const float gam = __ldg(gamma);
    const float* xb = x + (size_t)b * Cn * Ln;
    float* ob = out + (size_t)b * Cn * Ln;
    float* Tsm = reinterpret_cast<float*>(dsm + SM_V(0));   // [64][68] f32

    #pragma unroll
    for (int qt = 0; qt < 2; ++qt) {
        float l0s = lsum[qt][0], l1s = lsum[qt][1];
        l0s += __shfl_xor_sync(0xFFFFFFFF, l0s, 1);
        l0s += __shfl_xor_sync(0xFFFFFFFF, l0s, 2);
        l1s += __shfl_xor_sync(0xFFFFFFFF, l1s, 1);
        l1s += __shfl_xor_sync(0xFFFFFFFF, l1s, 2);
        {
            float2* ls = reinterpret_cast<float2*>(dsm + SM_LS + (w * 2 + qt) * 256);
            ls[lane] = make_float2(l0s, l1s);
            BAR_SYNC(barid, 64);
            const float2* lsp = reinterpret_cast<const float2*>(
                dsm + SM_LS + ((w ^ 1) * 2 + qt) * 256);
            float2 o = lsp[lane];
            l0s += o.x;
            l1s += o.y;
        }
        const float linv0 = 1.f / l0s;
        const float linv1 = 1.f / l1s;

        for (int h = 0; h < 2; ++h) {
            __syncthreads();
            if (ch == h) {
                int q = qg * 16 + (lane >> 2);
                #pragma unroll
                for (int nt = 0; nt < 8; ++nt) {
                    int cl = nt * 8 + (lane & 3) * 2;
                    Tsm[cl * 68 + q]           = of[qt][nt][0] * linv0;
                    Tsm[(cl + 1) * 68 + q]     = of[qt][nt][1] * linv0;
                    Tsm[cl * 68 + q + 8]       = of[qt][nt][2] * linv1;
                    Tsm[(cl + 1) * 68 + q + 8] = of[qt][nt][3] * linv1;
                }
            }
            __syncthreads();
            for (int idx = t; idx < 64 * 64; idx += 256) {
                int cl = idx >> 6, q = idx & 63;
                size_t off = (size_t)(ch_half * 128 + h * 64 + cl) * Ln + i0 + qt * 64 + q;
                ob[off] = gam * Tsm[cl * 68 + q] + xb[off];
            }
        }
    }
}

// ===========================================================================
extern "C" void kernel_launch(void* const* d_in, const int* in_sizes, int n_in,
                              void* d_out, int out_size)
{
    const float* x     = (const float*)d_in[0];
    const float* Wq    = (const float*)d_in[1];
    const float* bq    = (const float*)d_in[2];
    const float* Wk    = (const float*)d_in[3];
    const float* bk    = (const float*)d_in[4];
    const float* Wv    = (const float*)d_in[5];
    const float* bv    = (const float*)d_in[6];
    const float* gamma = (const float*)d_in[7];
    float* out = (float*)d_out;

    cudaFuncSetAttribute(qkv_gemm, cudaFuncAttributeMaxDynamicSharedMemorySize, QKV_SMEM);
    cudaFuncSetAttribute(attn_kernel, cudaFuncAttributeMaxDynamicSharedMemorySize, SM_TOTAL);

    qkv_gemm<<<dim3(Ln / 128, Bn), 512, QKV_SMEM>>>(x, Wq, bq, Wk, bk, Wv, bv);
    attn_kernel<<<dim3(Ln / 128, 2, Bn), 256, SM_TOTAL>>>(x, gamma, out);
}

// round 12
// speedup vs baseline: 2.7508x; 2.7508x over previous
#include <cuda_runtime.h>
#include <cuda_bf16.h>
#include <cuda_fp16.h>
#include <cstdint>

#define Bn 8
#define Cn 256
#define Ln 2048
#define Dn 32

// scratch (device globals; no cudaMalloc allowed)
__device__ __nv_bfloat16 g_Qb[Bn * Ln * Dn];   // [b][l][d]  pre-scaled by scale*log2e
__device__ __nv_bfloat16 g_Kb[Bn * Ln * Dn];   // [b][l][d]
__device__ __nv_bfloat16 g_Vb[Bn * Cn * Ln];   // [b][c][l]

// ============================ helpers ======================================
__device__ __forceinline__ uint32_t smem_to_u32(const void* p) {
    uint32_t a;
    asm("{ .reg .u64 t; cvta.to.shared.u64 t, %1; cvt.u32.u64 %0, t; }" : "=r"(a) : "l"(p));
    return a;
}
// Schraudolph fast 2^x: FFMA + F2I on the (near-idle) fma/cvt pipes instead of
// MUFU (rt 8), which is co-dominant with tensor in the QK->exp->PV chain.
// magic = 2^23 * (127 - 0.0436774) minimizes RMS error (~1.5%).
__device__ __forceinline__ float ex2f(float x) {
    return __int_as_float(__float2int_rn(fmaf(x, 8388608.0f, 1064866805.0f)));
}
#define CVT_BF16X2(res, a, b) \
    asm("cvt.rn.bf16x2.f32 %0, %1, %2;" : "=r"(res) : "f"(b), "f"(a))
#define CVT_F16X2(res, a, b) \
    asm("cvt.rn.f16x2.f32 %0, %1, %2;" : "=r"(res) : "f"(b), "f"(a))

__device__ __forceinline__ void ldmatrix_x4(uint32_t& r0, uint32_t& r1, uint32_t& r2, uint32_t& r3, uint32_t addr) {
    asm volatile("ldmatrix.sync.aligned.m8n8.x4.shared.b16 {%0,%1,%2,%3}, [%4];"
                 : "=r"(r0), "=r"(r1), "=r"(r2), "=r"(r3) : "r"(addr));
}
__device__ __forceinline__ void ldmatrix_x2(uint32_t& r0, uint32_t& r1, uint32_t addr) {
    asm volatile("ldmatrix.sync.aligned.m8n8.x2.shared.b16 {%0,%1}, [%2];"
                 : "=r"(r0), "=r"(r1) : "r"(addr));
}
__device__ __forceinline__ void mma_bf16(float& c0, float& c1, float& c2, float& c3,
                                         uint32_t a0, uint32_t a1, uint32_t a2, uint32_t a3,
                                         uint32_t b0, uint32_t b1) {
    asm volatile("mma.sync.aligned.m16n8k16.row.col.f32.bf16.bf16.f32 "
                 "{%0,%1,%2,%3}, {%4,%5,%6,%7}, {%8,%9}, {%0,%1,%2,%3};"
                 : "+f"(c0), "+f"(c1), "+f"(c2), "+f"(c3)
                 : "r"(a0), "r"(a1), "r"(a2), "r"(a3), "r"(b0), "r"(b1));
}
__device__ __forceinline__ void mma_fp16(float& c0, float& c1, float& c2, float& c3,
                                         uint32_t a0, uint32_t a1, uint32_t a2, uint32_t a3,
                                         uint32_t b0, uint32_t b1) {
    asm volatile("mma.sync.aligned.m16n8k16.row.col.f32.f16.f16.f32 "
                 "{%0,%1,%2,%3}, {%4,%5,%6,%7}, {%8,%9}, {%0,%1,%2,%3};"
                 : "+f"(c0), "+f"(c1), "+f"(c2), "+f"(c3)
                 : "r"(a0), "r"(a1), "r"(a2), "r"(a3), "r"(b0), "r"(b1));
}
__device__ __forceinline__ void cp_async16(uint32_t saddr, const void* gptr) {
    asm volatile("cp.async.cg.shared.global [%0], [%1], 16;" :: "r"(saddr), "l"(gptr));
}
#define CP_COMMIT() asm volatile("cp.async.commit_group;" ::: "memory")
#define CP_WAIT0()  asm volatile("cp.async.wait_group 0;" ::: "memory")
#define BAR_SYNC(id, n) asm volatile("bar.sync %0, %1;" :: "r"(id), "r"(n) : "memory")

// ===========================================================================
// Kernel 1: QKV projection as HMMA GEMM (W loaded fp32, cvt in-register).
// grid (L/128, B), 512 threads. Warp w: mg = w&1 (64 l), nh = w>>1 (40 rows).
// ===========================================================================
#define QKV_SMEM 69632

__global__ __launch_bounds__(512) void qkv_gemm(
    const float* __restrict__ x,
    const float* __restrict__ Wq, const float* __restrict__ bq,
    const float* __restrict__ Wk, const float* __restrict__ bk,
    const float* __restrict__ Wv, const float* __restrict__ bv)
{
    extern __shared__ __align__(16) char qsmraw[];
    uint32_t* xs = reinterpret_cast<uint32_t*>(qsmraw);

    const int b = blockIdx.y, l0 = blockIdx.x * 128, t = threadIdx.x;
    const float* xb = x + (size_t)b * Cn * Ln;

    for (int idx = t; idx < 128 * 128; idx += 512) {
        int cp = idx >> 7, l = idx & 127;
        float f0 = xb[(size_t)(2 * cp) * Ln + l0 + l];
        float f1 = xb[(size_t)(2 * cp + 1) * Ln + l0 + l];
        uint32_t p; CVT_F16X2(p, f0, f1);
        xs[l * 132 + cp] = p;
    }
    __syncthreads();

    const int w = t >> 5, lane = t & 31;
    const int mg = w & 1, nh = w >> 1;
    const int nbase = nh * 40;

    const float* wp[5];
    #pragma unroll
    for (int nt = 0; nt < 5; ++nt) {
        int n0 = nbase + nt * 8;
        const float* src;
        if (n0 < 32)      src = Wq + n0 * Cn;
        else if (n0 < 64) src = Wk + (n0 - 32) * Cn;
        else              src = Wv + (n0 - 64) * Cn;
        wp[nt] = src + (lane >> 2) * Cn + (lane & 3) * 2;
    }

    float of[4][5][4];
    #pragma unroll
    for (int m = 0; m < 4; ++m)
        #pragma unroll
        for (int n = 0; n < 5; ++n)
            #pragma unroll
            for (int k = 0; k < 4; ++k) of[m][n][k] = 0.f;

    const uint32_t abase = smem_to_u32(xs)
        + (uint32_t)((mg * 64 + (lane & 15)) * 132) * 4 + ((lane >> 4) & 1) * 16;

    for (int ks = 0; ks < 16; ++ks) {
        uint32_t aq[4][4];
        #pragma unroll
        for (int mt = 0; mt < 4; ++mt)
            ldmatrix_x4(aq[mt][0], aq[mt][1], aq[mt][2], aq[mt][3],
                        abase + (uint32_t)(mt * 16 * 132) * 4 + ks * 32);
        #pragma unroll
        for (int nt = 0; nt < 5; ++nt) {
            float2 wa = __ldg(reinterpret_cast<const float2*>(wp[nt] + ks * 16));
            float2 wb = __ldg(reinterpret_cast<const float2*>(wp[nt] + ks * 16 + 8));
            uint32_t b0, b1;
            CVT_F16X2(b0, wa.x, wa.y);
            CVT_F16X2(b1, wb.x, wb.y);
            #pragma unroll
            for (int mt = 0; mt < 4; ++mt)
                mma_fp16(of[mt][nt][0], of[mt][nt][1], of[mt][nt][2], of[mt][nt][3],
                         aq[mt][0], aq[mt][1], aq[mt][2], aq[mt][3], b0, b1);
        }
    }
    __syncthreads();

    __nv_bfloat16* vt = reinterpret_cast<__nv_bfloat16*>(qsmraw);   // [256][136]
    const float qs = 1.4426950408889634f * 0.17677669529663687f;    // log2e / sqrt(D)

    #pragma unroll
    for (int nt = 0; nt < 5; ++nt) {
        int n0 = nbase + nt * 8;
        int d = n0 + (lane & 3) * 2;
        float2 bs;
        if (n0 < 32)      bs = __ldg(reinterpret_cast<const float2*>(bq + d));
        else if (n0 < 64) bs = __ldg(reinterpret_cast<const float2*>(bk + d - 32));
        else              bs = __ldg(reinterpret_cast<const float2*>(bv + d - 64));
        #pragma unroll
        for (int mt = 0; mt < 4; ++mt) {
            const int ll = mg * 64 + mt * 16 + (lane >> 2);
            const int lq = l0 + ll;
            float v0 = of[mt][nt][0] + bs.x, v1 = of[mt][nt][1] + bs.y;
            float v2 = of[mt][nt][2] + bs.x, v3 = of[mt][nt][3] + bs.y;
            if (n0 < 32) {
                uint32_t p0, p1;
                CVT_BF16X2(p0, v0 * qs, v1 * qs);
                CVT_BF16X2(p1, v2 * qs, v3 * qs);
                *reinterpret_cast<uint32_t*>(&g_Qb[((size_t)b * Ln + lq) * Dn + d])     = p0;
                *reinterpret_cast<uint32_t*>(&g_Qb[((size_t)b * Ln + lq + 8) * Dn + d]) = p1;
            } else if (n0 < 64) {
                int dk = d - 32;
                uint32_t p0, p1;
                CVT_BF16X2(p0, v0, v1);
                CVT_BF16X2(p1, v2, v3);
                *reinterpret_cast<uint32_t*>(&g_Kb[((size_t)b * Ln + lq) * Dn + dk])     = p0;
                *reinterpret_cast<uint32_t*>(&g_Kb[((size_t)b * Ln + lq + 8) * Dn + dk]) = p1;
            } else {
                int c = d - 64;
                vt[c * 136 + ll]           = __float2bfloat16(v0);
                vt[(c + 1) * 136 + ll]     = __float2bfloat16(v1);
                vt[c * 136 + ll + 8]       = __float2bfloat16(v2);
                vt[(c + 1) * 136 + ll + 8] = __float2bfloat16(v3);
            }
        }
    }
    __syncthreads();

    __nv_bfloat16* Vg = g_Vb + (size_t)b * Cn * Ln;
    for (int idx = t; idx < 256 * 16; idx += 512) {
        int c = idx >> 4, k8 = idx & 15;
        *reinterpret_cast<uint4*>(Vg + (size_t)c * Ln + l0 + k8 * 8) =
            *reinterpret_cast<const uint4*>(&vt[c * 136 + k8 * 8]);
    }
}

// ===========================================================================
// Kernel 2: HMMA flash attention, TWO 64-q blocks per CTA, single wave.
// grid (L/128, 2, B) = 256 CTAs, 256 threads, 2 CTAs/SM. (R10 structure,
// exp moved off MUFU.)
// ===========================================================================
#define SM_PQ    0
#define SM_K(bi) (16384 + (bi) * 10240)
#define SM_V(bi) (36864 + (bi) * 34816)
#define SM_LS    106496
#define SM_TOTAL 110592

__global__ __launch_bounds__(256, 2) void attn_kernel(
    const float* __restrict__ x,
    const float* __restrict__ gamma,
    float* __restrict__ out)
{
    extern __shared__ __align__(16) char dsm[];
    const int b = blockIdx.z, ch_half = blockIdx.y, i0 = blockIdx.x * 128;
    const int t = threadIdx.x;
    const int w = t >> 5, lane = t & 31;
    const int qg = w >> 1, ch = w & 1;

    const uint32_t sbase = smem_to_u32(dsm);
    __nv_bfloat16* Qsm = reinterpret_cast<__nv_bfloat16*>(dsm + SM_PQ);

    const __nv_bfloat16* Qg = &g_Qb[((size_t)b * Ln + i0) * Dn];
    const __nv_bfloat16* Kg = &g_Kb[(size_t)b * Ln * Dn];
    const __nv_bfloat16* Vg = &g_Vb[((size_t)b * Cn + ch_half * 128) * Ln];

    // stage Q tile: 128 q x 32 d (512 uint4, 2/thread)
    #pragma unroll
    for (int i = 0; i < 2; ++i) {
        int idx = t + i * 256;
        int q = idx >> 2, dc = idx & 3;
        uint4 v = *reinterpret_cast<const uint4*>(Qg + (size_t)q * Dn + dc * 8);
        *reinterpret_cast<uint4*>(&Qsm[q * 40 + dc * 8]) = v;
    }

    // prologue: chunk 0. K: 512 cp (2/thread); V: 2048 cp (8/thread)
    {
        #pragma unroll
        for (int i = 0; i < 2; ++i) {
            int idx = t + i * 256;
            int j = idx >> 2, dc = idx & 3;
            cp_async16(sbase + SM_K(0) + j * 80 + dc * 16, Kg + (size_t)j * Dn + dc * 8);
        }
        #pragma unroll
        for (int i = 0; i < 8; ++i) {
            int idx = t + i * 256;
            int c = idx >> 4, jc = idx & 15;
            cp_async16(sbase + SM_V(0) + c * 272 + jc * 16, Vg + (size_t)c * Ln + jc * 8);
        }
    }
    CP_COMMIT();
    __syncthreads();

    // Q a-frags for both q-tiles (Q smem dead afterwards -> region becomes P slots)
    uint32_t aq[2][2][4];
    #pragma unroll
    for (int qt = 0; qt < 2; ++qt) {
        uint32_t base = sbase + SM_PQ
            + ((qt * 64 + qg * 16 + (lane & 15)) * 40 + ((lane >> 4) & 1) * 8) * 2;
        ldmatrix_x4(aq[qt][0][0], aq[qt][0][1], aq[qt][0][2], aq[qt][0][3], base);
        ldmatrix_x4(aq[qt][1][0], aq[qt][1][1], aq[qt][1][2], aq[qt][1][3], base + 32);
    }

    const uint32_t kb_lane = (lane & 7) * 80 + ((lane >> 3) & 1) * 16;
    const uint32_t vb_lane = (lane & 7) * 272 + (lane >> 3) * 16;
    const uint32_t myslot  = SM_PQ + w * 2048 + lane * 16;
    const uint32_t pairslot = SM_PQ + (uint32_t)(qg * 2 + (ch ^ 1)) * 2048 + lane * 16;
    const int barid = 1 + qg;

    float of[2][8][4];
    #pragma unroll
    for (int qt = 0; qt < 2; ++qt)
        #pragma unroll
        for (int n = 0; n < 8; ++n)
            #pragma unroll
            for (int k = 0; k < 4; ++k) of[qt][n][k] = 0.f;
    float lsum[2][2] = {{0.f, 0.f}, {0.f, 0.f}};

// QK for q-tile QT over own 64-j half -> pa + lsum, then STS to my slot
#define QK_PHASE(QT) do {                                                      \
    const uint32_t kh = ks_u + (uint32_t)(ch * 64) * 80 + kb_lane;             \
    _Pragma("unroll")                                                          \
    for (int jt = 0; jt < 8; ++jt) {                                           \
        float s0 = 0.f, s1 = 0.f, s2 = 0.f, s3 = 0.f;                          \
        uint32_t b0, b1;                                                       \
        uint32_t kaddr = kh + jt * 640;                                        \
        ldmatrix_x2(b0, b1, kaddr);                                            \
        mma_bf16(s0, s1, s2, s3, aq[QT][0][0], aq[QT][0][1],                   \
                 aq[QT][0][2], aq[QT][0][3], b0, b1);                          \
        ldmatrix_x2(b0, b1, kaddr + 32);                                       \
        mma_bf16(s0, s1, s2, s3, aq[QT][1][0], aq[QT][1][1],                   \
                 aq[QT][1][2], aq[QT][1][3], b0, b1);                          \
        float e0 = ex2f(s0), e1 = ex2f(s1), e2 = ex2f(s2), e3 = ex2f(s3);      \
        lsum[QT][0] += e0 + e1;                                                \
        lsum[QT][1] += e2 + e3;                                                \
        uint32_t plo, phi;                                                     \
        CVT_BF16X2(plo, e0, e1);                                               \
        CVT_BF16X2(phi, e2, e3);                                               \
        int pt = jt >> 1;                                                      \
        if ((jt & 1) == 0) { pa[pt][0] = plo; pa[pt][1] = phi; }               \
        else               { pa[pt][2] = plo; pa[pt][3] = phi; }               \
    }                                                                          \
    _Pragma("unroll")                                                          \
    for (int pt = 0; pt < 4; ++pt)                                             \
        *reinterpret_cast<uint4*>(dsm + myslot + pt * 512) =                   \
            make_uint4(pa[pt][0], pa[pt][1], pa[pt][2], pa[pt][3]);            \
} while (0)

// PV for q-tile QT, j-half H, with fragment array PF
#define PV_PHASE(QT, H, PF) do {                                               \
    _Pragma("unroll")                                                          \
    for (int nt = 0; nt < 8; ++nt) {                                           \
        uint32_t vbase = vs_u + (uint32_t)(ch * 64 + nt * 8) * 272             \
                       + (H) * 128 + vb_lane;                                  \
        uint32_t b0, b1, b2, b3;                                               \
        ldmatrix_x4(b0, b1, b2, b3, vbase);                                    \
        mma_bf16(of[QT][nt][0], of[QT][nt][1], of[QT][nt][2], of[QT][nt][3],   \
                 PF[0][0], PF[0][1], PF[0][2], PF[0][3], b0, b1);              \
        mma_bf16(of[QT][nt][0], of[QT][nt][1], of[QT][nt][2], of[QT][nt][3],   \
                 PF[1][0], PF[1][1], PF[1][2], PF[1][3], b2, b3);              \
        ldmatrix_x4(b0, b1, b2, b3, vbase + 64);                               \
        mma_bf16(of[QT][nt][0], of[QT][nt][1], of[QT][nt][2], of[QT][nt][3],   \
                 PF[2][0], PF[2][1], PF[2][2], PF[2][3], b0, b1);              \
        mma_bf16(of[QT][nt][0], of[QT][nt][1], of[QT][nt][2], of[QT][nt][3],   \
                 PF[3][0], PF[3][1], PF[3][2], PF[3][3], b2, b3);              \
    }                                                                          \
} while (0)

#define LOAD_PAIR_P(PF) do {                                                   \
    _Pragma("unroll")                                                          \
    for (int pt = 0; pt < 4; ++pt) {                                           \
        uint4 v = *reinterpret_cast<const uint4*>(dsm + pairslot + pt * 512);  \
        PF[pt][0] = v.x; PF[pt][1] = v.y; PF[pt][2] = v.z; PF[pt][3] = v.w;    \
    }                                                                          \
} while (0)

    for (int cidx = 0; cidx < Ln / 128; ++cidx) {
        CP_WAIT0();
        __syncthreads();   // buffers + P slots free for this chunk

        // issue chunk cidx+1
        if (cidx + 1 < Ln / 128) {
            int j0n = (cidx + 1) * 128;
            int bi = (cidx + 1) & 1;
            #pragma unroll
            for (int i = 0; i < 2; ++i) {
                int idx = t + i * 256;
                int j = idx >> 2, dc = idx & 3;
                cp_async16(sbase + SM_K(bi) + j * 80 + dc * 16,
                           Kg + (size_t)(j0n + j) * Dn + dc * 8);
            }
            #pragma unroll
            for (int i = 0; i < 8; ++i) {
                int idx = t + i * 256;
                int c = idx >> 4, jc = idx & 15;
                cp_async16(sbase + SM_V(bi) + c * 272 + jc * 16,
                           Vg + (size_t)c * Ln + j0n + jc * 8);
            }
        }
        CP_COMMIT();

        const uint32_t ks_u = sbase + SM_K(cidx & 1);
        const uint32_t vs_u = sbase + SM_V(cidx & 1);

        uint32_t pa[4][4], pf[4][4];

        // --- q-tile 0 ---
        QK_PHASE(0);
        PV_PHASE(0, ch, pa);          // own j-half
        BAR_SYNC(barid, 64);          // pa0 published by both warps of pair
        LOAD_PAIR_P(pf);
        BAR_SYNC(barid, 64);          // pf0 consumed -> slot may be overwritten
        PV_PHASE(0, ch ^ 1, pf);      // other j-half

        // --- q-tile 1 ---
        QK_PHASE(1);
        PV_PHASE(1, ch, pa);
        BAR_SYNC(barid, 64);          // pa1 published
        LOAD_PAIR_P(pf);
        PV_PHASE(1, ch ^ 1, pf);
    }

    const float gam = __ldg(gamma);
    const float* xb = x + (size_t)b * Cn * Ln;
    float* ob = out + (size_t)b * Cn * Ln;
    float* Tsm = reinterpret_cast<float*>(dsm + SM_V(0));   // [64][68] f32

    #pragma unroll
    for (int qt = 0; qt < 2; ++qt) {
        float l0s = lsum[qt][0], l1s = lsum[qt][1];
        l0s += __shfl_xor_sync(0xFFFFFFFF, l0s, 1);
        l0s += __shfl_xor_sync(0xFFFFFFFF, l0s, 2);
        l1s += __shfl_xor_sync(0xFFFFFFFF, l1s, 1);
        l1s += __shfl_xor_sync(0xFFFFFFFF, l1s, 2);
        {
            float2* ls = reinterpret_cast<float2*>(dsm + SM_LS + (w * 2 + qt) * 256);
            ls[lane] = make_float2(l0s, l1s);
            BAR_SYNC(barid, 64);
            const float2* lsp = reinterpret_cast<const float2*>(
                dsm + SM_LS + ((w ^ 1) * 2 + qt) * 256);
            float2 o = lsp[lane];
            l0s += o.x;
            l1s += o.y;
        }
        const float linv0 = 1.f / l0s;
        const float linv1 = 1.f / l1s;

        for (int h = 0; h < 2; ++h) {
            __syncthreads();
            if (ch == h) {
                int q = qg * 16 + (lane >> 2);
                #pragma unroll
                for (int nt = 0; nt < 8; ++nt) {
                    int cl = nt * 8 + (lane & 3) * 2;
                    Tsm[cl * 68 + q]           = of[qt][nt][0] * linv0;
                    Tsm[(cl + 1) * 68 + q]     = of[qt][nt][1] * linv0;
                    Tsm[cl * 68 + q + 8]       = of[qt][nt][2] * linv1;
                    Tsm[(cl + 1) * 68 + q + 8] = of[qt][nt][3] * linv1;
                }
            }
            __syncthreads();
            for (int idx = t; idx < 64 * 64; idx += 256) {
                int cl = idx >> 6, q = idx & 63;
                size_t off = (size_t)(ch_half * 128 + h * 64 + cl) * Ln + i0 + qt * 64 + q;
                ob[off] = gam * Tsm[cl * 68 + q] + xb[off];
            }
        }
    }
}

// ===========================================================================
extern "C" void kernel_launch(void* const* d_in, const int* in_sizes, int n_in,
                              void* d_out, int out_size)
{
    const float* x     = (const float*)d_in[0];
    const float* Wq    = (const float*)d_in[1];
    const float* bq    = (const float*)d_in[2];
    const float* Wk    = (const float*)d_in[3];
    const float* bk    = (const float*)d_in[4];
    const float* Wv    = (const float*)d_in[5];
    const float* bv    = (const float*)d_in[6];
    const float* gamma = (const float*)d_in[7];
    float* out = (float*)d_out;

    cudaFuncSetAttribute(qkv_gemm, cudaFuncAttributeMaxDynamicSharedMemorySize, QKV_SMEM);
    cudaFuncSetAttribute(attn_kernel, cudaFuncAttributeMaxDynamicSharedMemorySize, SM_TOTAL);

    qkv_gemm<<<dim3(Ln / 128, Bn), 512, QKV_SMEM>>>(x, Wq, bq, Wk, bk, Wv, bv);
    attn_kernel<<<dim3(Ln / 128, 2, Bn), 256, SM_TOTAL>>>(x, gamma, out);
}